// round 4
// baseline (speedup 1.0000x reference)
#include <cuda_runtime.h>
#include <math.h>

// Problem shapes (fixed by setup_inputs): B=2, L=2048, E=512, window=64
#define B_  2
#define L_  2048
#define E_  512
#define WIN 64
#define NW  129          // 2*WIN + 1

// ---------------- scratch (device globals; no cudaMalloc allowed) ----------
__device__ float g_q[B_ * L_ * E_];
__device__ float g_k[B_ * L_ * E_];
__device__ float g_v[B_ * L_ * E_];

// ============================================================================
// QKV GEMM: C[m, f] = sum_e X[m, e] * W[f, e] + bias[f]
// M = B*L = 4096, N = 512, K = 512.  blockIdx.z selects q/k/v.
// 128x128 tile, BK=16, 256 threads, 8x8 per thread.
// ============================================================================
#define BM 128
#define BN 128
#define BK 16
#define ASTR 132   // padded smem row stride (floats); 132*4 % 16 == 0

__global__ __launch_bounds__(256) void qkv_gemm(
    const float* __restrict__ X,
    const float* __restrict__ W0, const float* __restrict__ b0,
    const float* __restrict__ W1, const float* __restrict__ b1,
    const float* __restrict__ W2, const float* __restrict__ b2)
{
    __shared__ __align__(16) float As[BK][ASTR];
    __shared__ __align__(16) float Bs[BK][ASTR];

    const float* W; const float* bias; float* C;
    int z = blockIdx.z;
    if (z == 0)      { W = W0; bias = b0; C = g_q; }
    else if (z == 1) { W = W1; bias = b1; C = g_k; }
    else             { W = W2; bias = b2; C = g_v; }

    const int m0 = blockIdx.x * BM;
    const int n0 = blockIdx.y * BN;
    const int t  = threadIdx.x;
    const int tx = t & 15;       // 0..15  -> N direction
    const int ty = t >> 4;       // 0..15  -> M direction

    const int lr = t >> 2;       // 0..63 load row
    const int lk = (t & 3) * 4;  // 0,4,8,12 load k-offset

    float acc[8][8];
    #pragma unroll
    for (int i = 0; i < 8; i++)
        #pragma unroll
        for (int j = 0; j < 8; j++) acc[i][j] = 0.f;

    for (int k0 = 0; k0 < E_; k0 += BK) {
        // load A (128 x 16) and B (128 x 16), transposed into smem
        #pragma unroll
        for (int i = 0; i < 2; i++) {
            int row = lr + i * 64;
            float4 a = *(const float4*)&X[(m0 + row) * E_ + k0 + lk];
            As[lk + 0][row] = a.x; As[lk + 1][row] = a.y;
            As[lk + 2][row] = a.z; As[lk + 3][row] = a.w;
            float4 b = *(const float4*)&W[(n0 + row) * E_ + k0 + lk];
            Bs[lk + 0][row] = b.x; Bs[lk + 1][row] = b.y;
            Bs[lk + 2][row] = b.z; Bs[lk + 3][row] = b.w;
        }
        __syncthreads();

        #pragma unroll
        for (int k = 0; k < BK; k++) {
            float a[8], b[8];
            *(float4*)(a)     = *(const float4*)&As[k][ty * 8];
            *(float4*)(a + 4) = *(const float4*)&As[k][ty * 8 + 4];
            *(float4*)(b)     = *(const float4*)&Bs[k][tx * 8];
            *(float4*)(b + 4) = *(const float4*)&Bs[k][tx * 8 + 4];
            #pragma unroll
            for (int i = 0; i < 8; i++)
                #pragma unroll
                for (int j = 0; j < 8; j++)
                    acc[i][j] = fmaf(a[i], b[j], acc[i][j]);
        }
        __syncthreads();
    }

    float bb[8];
    #pragma unroll
    for (int j = 0; j < 8; j++) bb[j] = bias[n0 + tx * 8 + j];

    #pragma unroll
    for (int i = 0; i < 8; i++) {
        int row = m0 + ty * 8 + i;
        float4 r0, r1;
        r0.x = acc[i][0] + bb[0]; r0.y = acc[i][1] + bb[1];
        r0.z = acc[i][2] + bb[2]; r0.w = acc[i][3] + bb[3];
        r1.x = acc[i][4] + bb[4]; r1.y = acc[i][5] + bb[5];
        r1.z = acc[i][6] + bb[6]; r1.w = acc[i][7] + bb[7];
        *(float4*)&C[row * E_ + n0 + tx * 8]     = r0;
        *(float4*)&C[row * E_ + n0 + tx * 8 + 4] = r1;
    }
}

// ============================================================================
// Banded local attention.
// Block = 32 queries of one batch. Key rows needed: [q0-64, q0+95] -> 160 rows.
// Phase 1: scores[32][160] = Q_tile @ K_rows^T  (accumulated over 4 E-chunks)
// Softmax over valid band (wj = r - qi in [0,128], key index in [0,L)).
// Phase 2: out[32][E] = probs[32][160] @ V_rows (per E-chunk).
// ============================================================================
#define TQ   32
#define NR   160          // TQ + 2*WIN
#define ECH  128          // E chunk size (E_/ECH = 4 chunks)
#define QST  132          // q smem stride
#define KST  133          // k smem stride (odd -> conflict-free strided reads)
#define VST  132          // v smem stride (16B-aligned rows for float4 reads)
#define SST  161          // scores smem stride

#define Q_OFF   0
#define KV_OFF  (TQ * QST)                 // 4224 floats
#define SC_OFF  (KV_OFF + NR * KST)        // 4224 + 21280 = 25504 floats
#define SMEM_FLOATS (SC_OFF + TQ * SST)    // 30656 floats = 122624 bytes

__global__ __launch_bounds__(256) void local_attn(float* __restrict__ out)
{
    extern __shared__ float smem[];
    float* qS  = smem + Q_OFF;
    float* kvS = smem + KV_OFF;
    float* scS = smem + SC_OFF;

    const int q0 = blockIdx.x * TQ;
    const int b  = blockIdx.y;
    const int t  = threadIdx.x;
    const int tx = t & 31;       // lane
    const int ty = t >> 5;       // warp 0..7

    const float* gq = g_q + b * (L_ * E_);
    const float* gk = g_k + b * (L_ * E_);
    const float* gv = g_v + b * (L_ * E_);

    // ---------- Phase 1: scores = Q @ K^T, accumulated over E chunks --------
    float acc[4][5];
    #pragma unroll
    for (int i = 0; i < 4; i++)
        #pragma unroll
        for (int j = 0; j < 5; j++) acc[i][j] = 0.f;

    for (int ec = 0; ec < E_; ec += ECH) {
        // load q tile [32][128]
        #pragma unroll
        for (int it = 0; it < (TQ * (ECH / 4)) / 256; it++) {
            int idx = t + it * 256;
            int row = idx >> 5, c = (idx & 31) * 4;
            float4 v = *(const float4*)&gq[(q0 + row) * E_ + ec + c];
            *(float4*)&qS[row * QST + c] = v;
        }
        // load k rows [160][128] (zero-fill out-of-sequence rows)
        #pragma unroll
        for (int it = 0; it < (NR * (ECH / 4)) / 256; it++) {
            int idx = t + it * 256;
            int row = idx >> 5, c = (idx & 31) * 4;
            int kg = q0 - WIN + row;
            float4 v = make_float4(0.f, 0.f, 0.f, 0.f);
            if (kg >= 0 && kg < L_)
                v = *(const float4*)&gk[kg * E_ + ec + c];
            float* dst = &kvS[row * KST + c];   // KST odd: scalar stores
            dst[0] = v.x; dst[1] = v.y; dst[2] = v.z; dst[3] = v.w;
        }
        __syncthreads();

        #pragma unroll 4
        for (int e = 0; e < ECH; e++) {
            float a[4], kk[5];
            #pragma unroll
            for (int i = 0; i < 4; i++) a[i] = qS[(ty * 4 + i) * QST + e];
            #pragma unroll
            for (int j = 0; j < 5; j++) kk[j] = kvS[(tx + 32 * j) * KST + e];
            #pragma unroll
            for (int i = 0; i < 4; i++)
                #pragma unroll
                for (int j = 0; j < 5; j++)
                    acc[i][j] = fmaf(a[i], kk[j], acc[i][j]);
        }
        __syncthreads();
    }

    // write raw scores to smem
    #pragma unroll
    for (int i = 0; i < 4; i++)
        #pragma unroll
        for (int j = 0; j < 5; j++)
            scS[(ty * 4 + i) * SST + tx + 32 * j] = acc[i][j];
    __syncthreads();

    // ---------- Softmax: 8 lanes per query, 20 elements per lane ------------
    {
        const float inv_sqrt_e = 0.04419417382415922f;  // 1/sqrt(512)
        const int qi  = t >> 3;
        const int sub = t & 7;
        float vals[20];
        float m = -INFINITY;
        #pragma unroll
        for (int u = 0; u < 20; u++) {
            int r  = sub * 20 + u;
            int wj = r - qi;
            int kg = q0 + r - WIN;
            bool valid = (wj >= 0) && (wj <= 2 * WIN) && (kg >= 0) && (kg < L_);
            float s = valid ? scS[qi * SST + r] * inv_sqrt_e : -INFINITY;
            vals[u] = s;
            m = fmaxf(m, s);
        }
        #pragma unroll
        for (int o = 1; o < 8; o <<= 1)
            m = fmaxf(m, __shfl_xor_sync(0xffffffffu, m, o, 8));
        float ssum = 0.f;
        #pragma unroll
        for (int u = 0; u < 20; u++) {
            float e = (vals[u] == -INFINITY) ? 0.f : __expf(vals[u] - m);
            vals[u] = e;
            ssum += e;
        }
        #pragma unroll
        for (int o = 1; o < 8; o <<= 1)
            ssum += __shfl_xor_sync(0xffffffffu, ssum, o, 8);
        float inv = 1.f / ssum;
        #pragma unroll
        for (int u = 0; u < 20; u++)
            scS[qi * SST + sub * 20 + u] = vals[u] * inv;
    }
    __syncthreads();

    // ---------- Phase 2: out = probs @ V, per E chunk ------------------------
    float* gout = out + b * (L_ * E_);
    for (int ec = 0; ec < E_; ec += ECH) {
        // load v rows [160][128] with float4-friendly stride
        #pragma unroll
        for (int it = 0; it < (NR * (ECH / 4)) / 256; it++) {
            int idx = t + it * 256;
            int row = idx >> 5, c = (idx & 31) * 4;
            int kg = q0 - WIN + row;
            float4 v = make_float4(0.f, 0.f, 0.f, 0.f);
            if (kg >= 0 && kg < L_)
                v = *(const float4*)&gv[kg * E_ + ec + c];
            *(float4*)&kvS[row * VST + c] = v;
        }
        __syncthreads();

        float o[4][4];
        #pragma unroll
        for (int i = 0; i < 4; i++)
            #pragma unroll
            for (int j = 0; j < 4; j++) o[i][j] = 0.f;

        #pragma unroll 2
        for (int r = 0; r < NR; r++) {
            float4 vv = *(const float4*)&kvS[r * VST + tx * 4];
            float p[4];
            #pragma unroll
            for (int i = 0; i < 4; i++) p[i] = scS[(ty * 4 + i) * SST + r];
            #pragma unroll
            for (int i = 0; i < 4; i++) {
                o[i][0] = fmaf(p[i], vv.x, o[i][0]);
                o[i][1] = fmaf(p[i], vv.y, o[i][1]);
                o[i][2] = fmaf(p[i], vv.z, o[i][2]);
                o[i][3] = fmaf(p[i], vv.w, o[i][3]);
            }
        }

        #pragma unroll
        for (int i = 0; i < 4; i++) {
            float4 w;
            w.x = o[i][0]; w.y = o[i][1]; w.z = o[i][2]; w.w = o[i][3];
            *(float4*)&gout[(q0 + ty * 4 + i) * E_ + ec + tx * 4] = w;
        }
        __syncthreads();
    }
}

// ============================================================================
extern "C" void kernel_launch(void* const* d_in, const int* in_sizes, int n_in,
                              void* d_out, int out_size)
{
    const float* x  = (const float*)d_in[0];
    const float* Wq = (const float*)d_in[1];
    const float* bq = (const float*)d_in[2];
    const float* Wk = (const float*)d_in[3];
    const float* bk = (const float*)d_in[4];
    const float* Wv = (const float*)d_in[5];
    const float* bv = (const float*)d_in[6];
    float* out = (float*)d_out;

    // QKV projections: grid (M/128, N/128, 3)
    dim3 ggrid((B_ * L_) / BM, E_ / BN, 3);
    qkv_gemm<<<ggrid, 256>>>(x, Wq, bq, Wk, bk, Wv, bv);

    // Attention: 122.6 KB dynamic smem -> raise the limit (idempotent)
    static const size_t smem_bytes = SMEM_FLOATS * sizeof(float);
    cudaFuncSetAttribute(local_attn, cudaFuncAttributeMaxDynamicSharedMemorySize,
                         (int)smem_bytes);
    dim3 agrid(L_ / TQ, B_);
    local_attn<<<agrid, 256, smem_bytes>>>(out);
}

// round 10
// speedup vs baseline: 1.7567x; 1.7567x over previous
#include <cuda_runtime.h>
#include <cuda_bf16.h>
#include <math.h>
#include <stdint.h>

// Problem shapes (fixed by setup_inputs): B=2, L=2048, E=512, window=64
#define B_  2
#define L_  2048
#define E_  512
#define WIN 64
#define NW  129          // 2*WIN + 1

// ---------------- scratch (device globals; no cudaMalloc allowed) ----------
__device__ float g_q[B_ * L_ * E_];
__device__ float g_k[B_ * L_ * E_];
__device__ float g_v[B_ * L_ * E_];

// ============================================================================
// Warp-level tensor-core primitives (mma.sync / ldmatrix: baseline PTX,
// no sm_103a-only features -- the harness compiles via compute_103).
// ============================================================================
static __device__ __forceinline__ uint32_t smem_u32(const void* p) {
    uint32_t a;
    asm("{ .reg .u64 t; cvta.to.shared.u64 t, %1; cvt.u32.u64 %0, t; }"
        : "=r"(a) : "l"(p));
    return a;
}

static __device__ __forceinline__ void ldsm_x4(uint32_t (&r)[4], uint32_t addr)
{
    asm volatile("ldmatrix.sync.aligned.m8n8.x4.shared.b16 {%0,%1,%2,%3}, [%4];"
        : "=r"(r[0]), "=r"(r[1]), "=r"(r[2]), "=r"(r[3]) : "r"(addr));
}

static __device__ __forceinline__ void mma16816(
    float (&c)[4], const uint32_t (&a)[4], uint32_t b0, uint32_t b1)
{
    asm volatile(
        "mma.sync.aligned.m16n8k16.row.col.f32.bf16.bf16.f32 "
        "{%0,%1,%2,%3}, {%4,%5,%6,%7}, {%8,%9}, {%0,%1,%2,%3};"
        : "+f"(c[0]), "+f"(c[1]), "+f"(c[2]), "+f"(c[3])
        : "r"(a[0]), "r"(a[1]), "r"(a[2]), "r"(a[3]), "r"(b0), "r"(b1));
}

// fp32 -> (bf16 hi, bf16 lo) split: x ~= hi + lo, lo error ~2^-16 relative
static __device__ __forceinline__ void cvt_split(float4 f, uint2& hi, uint2& lo)
{
    float v[4] = {f.x, f.y, f.z, f.w};
    unsigned short h[4], l[4];
#pragma unroll
    for (int i = 0; i < 4; i++) {
        __nv_bfloat16 hb = __float2bfloat16(v[i]);
        float r = v[i] - __bfloat162float(hb);
        __nv_bfloat16 lb = __float2bfloat16(r);
        h[i] = __bfloat16_as_ushort(hb);
        l[i] = __bfloat16_as_ushort(lb);
    }
    hi.x = (uint32_t)h[0] | ((uint32_t)h[1] << 16);
    hi.y = (uint32_t)h[2] | ((uint32_t)h[3] << 16);
    lo.x = (uint32_t)l[0] | ((uint32_t)l[1] << 16);
    lo.y = (uint32_t)l[2] | ((uint32_t)l[3] << 16);
}

// ============================================================================
// QKV GEMM on tensor cores (mma.sync bf16, split precision ~ fp32 accuracy).
// C[m, f] = sum_e X[m, e] * W[f, e] + bias[f];  M=4096, N=512, K=512.
// CTA: 128x128 tile, K chunks of 64. Smem: A_hi/A_lo/B_hi/B_lo bf16 tiles,
// row stride 72 bf16 (144B) -> conflict-free ldmatrix (4r words mod 32).
// 8 warps = 2(M) x 4(N); warp tile 64x32 = 4 m16 x 4 n8 fragments.
// Splits accumulated: Ahi*Bhi + Ahi*Blo + Alo*Bhi (residual ~2^-16).
// ============================================================================
#define BKC   64                      // K per chunk
#define STRH  72                      // smem row stride (bf16 units)
#define TILEB (128 * STRH * 2)        // bytes per bf16 tile = 18432
#define QT_SMEM (4 * TILEB)           // 73728 bytes

__global__ __launch_bounds__(256) void qkv_tc(
    const float* __restrict__ X,
    const float* __restrict__ W0, const float* __restrict__ b0,
    const float* __restrict__ W1, const float* __restrict__ b1,
    const float* __restrict__ W2, const float* __restrict__ b2)
{
    extern __shared__ __align__(16) char smem[];
    const uint32_t sb = smem_u32(smem);
    const uint32_t sAhi = sb;
    const uint32_t sAlo = sb + TILEB;
    const uint32_t sBhi = sb + 2 * TILEB;
    const uint32_t sBlo = sb + 3 * TILEB;

    const float* W; const float* bias; float* C;
    const int z = blockIdx.z;
    if (z == 0)      { W = W0; bias = b0; C = g_q; }
    else if (z == 1) { W = W1; bias = b1; C = g_k; }
    else             { W = W2; bias = b2; C = g_v; }

    const int m0  = blockIdx.x * 128;
    const int n0  = blockIdx.y * 128;
    const int t   = threadIdx.x;
    const int wid = t >> 5;
    const int lid = t & 31;
    const int wm  = wid & 1;          // M half (64 rows)
    const int wn  = wid >> 1;         // N quarter (32 cols)

    float acc[4][4][4];
#pragma unroll
    for (int mi = 0; mi < 4; mi++)
#pragma unroll
        for (int ni = 0; ni < 4; ni++)
#pragma unroll
            for (int r = 0; r < 4; r++) acc[mi][ni][r] = 0.f;

    // ldmatrix lane addressing (precomputed offsets within a 16x16 block)
    const int g = lid >> 3;           // 0..3 (8-lane group)
    const int r8 = lid & 7;
    // A x4: row = (g&1)*8 + r8 ; kcol = (g>>1)*8
    const uint32_t aLaneOff = (uint32_t)((((g & 1) * 8 + r8) * STRH + (g >> 1) * 8) * 2);
    // B x4: n   = (g>>1)*8 + r8 ; kcol = (g&1)*8
    const uint32_t bLaneOff = (uint32_t)((((g >> 1) * 8 + r8) * STRH + (g & 1) * 8) * 2);

    for (int ck = 0; ck < 8; ck++) {
        const int k0 = ck * BKC;

        // ---- load + split-convert A (128 x 64) and B (128 x 64) ------------
#pragma unroll
        for (int it = 0; it < 8; it++) {
            int idx = t + it * 256;
            int row = idx >> 4, c4 = idx & 15;
            uint32_t off = (uint32_t)(row * (STRH * 2) + c4 * 8);
            float4 a = *(const float4*)&X[(m0 + row) * E_ + k0 + c4 * 4];
            uint2 hi, lo; cvt_split(a, hi, lo);
            *(uint2*)(smem + off)         = hi;
            *(uint2*)(smem + TILEB + off) = lo;
        }
#pragma unroll
        for (int it = 0; it < 8; it++) {
            int idx = t + it * 256;
            int row = idx >> 4, c4 = idx & 15;
            uint32_t off = (uint32_t)(row * (STRH * 2) + c4 * 8);
            float4 w = *(const float4*)&W[(n0 + row) * E_ + k0 + c4 * 4];
            uint2 hi, lo; cvt_split(w, hi, lo);
            *(uint2*)(smem + 2 * TILEB + off) = hi;
            *(uint2*)(smem + 3 * TILEB + off) = lo;
        }
        __syncthreads();

        // ---- MMA phase: 4 k16-steps x 3 splits -----------------------------
#pragma unroll
        for (int kk = 0; kk < 4; kk++) {
            const uint32_t kOff = (uint32_t)(kk * 16 * 2);
            uint32_t aH[4][4], aL[4][4], bH[2][4], bL[2][4];
#pragma unroll
            for (int mi = 0; mi < 4; mi++) {
                uint32_t rowOff = (uint32_t)((wm * 64 + mi * 16) * (STRH * 2));
                ldsm_x4(aH[mi], sAhi + rowOff + kOff + aLaneOff);
                ldsm_x4(aL[mi], sAlo + rowOff + kOff + aLaneOff);
            }
#pragma unroll
            for (int nj = 0; nj < 2; nj++) {
                uint32_t rowOff = (uint32_t)((wn * 32 + nj * 16) * (STRH * 2));
                ldsm_x4(bH[nj], sBhi + rowOff + kOff + bLaneOff);
                ldsm_x4(bL[nj], sBlo + rowOff + kOff + bLaneOff);
            }
#pragma unroll
            for (int mi = 0; mi < 4; mi++)
#pragma unroll
                for (int ni = 0; ni < 4; ni++) {
                    uint32_t b0r = bH[ni >> 1][(ni & 1) * 2];
                    uint32_t b1r = bH[ni >> 1][(ni & 1) * 2 + 1];
                    mma16816(acc[mi][ni], aH[mi], b0r, b1r);       // hi*hi
                    uint32_t l0 = bL[ni >> 1][(ni & 1) * 2];
                    uint32_t l1 = bL[ni >> 1][(ni & 1) * 2 + 1];
                    mma16816(acc[mi][ni], aH[mi], l0, l1);         // hi*lo
                    mma16816(acc[mi][ni], aL[mi], b0r, b1r);       // lo*hi
                }
        }
        __syncthreads();
    }

    // ---- epilogue: bias add + fp32 store -----------------------------------
    const int qg = lid >> 2;          // 0..7 (row within m16 fragment)
    const int qi = lid & 3;           // 0..3 (col pair within n8)
#pragma unroll
    for (int ni = 0; ni < 4; ni++) {
        int col = n0 + wn * 32 + ni * 8 + qi * 2;
        float2 bb = *(const float2*)&bias[col];
#pragma unroll
        for (int mi = 0; mi < 4; mi++) {
            int row = m0 + wm * 64 + mi * 16 + qg;
            float2 o0, o1;
            o0.x = acc[mi][ni][0] + bb.x;  o0.y = acc[mi][ni][1] + bb.y;
            o1.x = acc[mi][ni][2] + bb.x;  o1.y = acc[mi][ni][3] + bb.y;
            *(float2*)&C[(size_t)row * E_ + col]       = o0;
            *(float2*)&C[(size_t)(row + 8) * E_ + col] = o1;
        }
    }
}

// ============================================================================
// Banded local attention (unchanged from the passing round-4 kernel).
// Block = 32 queries of one batch. Key rows needed: [q0-64, q0+95] -> 160 rows.
// ============================================================================
#define TQ   32
#define NR   160          // TQ + 2*WIN
#define ECH  128          // E chunk size (E_/ECH = 4 chunks)
#define QST  132          // q smem stride
#define KST  133          // k smem stride (odd -> conflict-free strided reads)
#define VST  132          // v smem stride (16B-aligned rows for float4 reads)
#define SST  161          // scores smem stride

#define Q_OFF   0
#define KV_OFF  (TQ * QST)                 // 4224 floats
#define SC_OFF  (KV_OFF + NR * KST)        // 25504 floats
#define SMEM_FLOATS (SC_OFF + TQ * SST)    // 30656 floats = 122624 bytes

__global__ __launch_bounds__(256) void local_attn(float* __restrict__ out)
{
    extern __shared__ float fsmem[];
    float* qS  = fsmem + Q_OFF;
    float* kvS = fsmem + KV_OFF;
    float* scS = fsmem + SC_OFF;

    const int q0 = blockIdx.x * TQ;
    const int b  = blockIdx.y;
    const int t  = threadIdx.x;
    const int tx = t & 31;       // lane
    const int ty = t >> 5;       // warp 0..7

    const float* gq = g_q + b * (L_ * E_);
    const float* gk = g_k + b * (L_ * E_);
    const float* gv = g_v + b * (L_ * E_);

    // ---------- Phase 1: scores = Q @ K^T, accumulated over E chunks --------
    float acc[4][5];
    #pragma unroll
    for (int i = 0; i < 4; i++)
        #pragma unroll
        for (int j = 0; j < 5; j++) acc[i][j] = 0.f;

    for (int ec = 0; ec < E_; ec += ECH) {
        #pragma unroll
        for (int it = 0; it < (TQ * (ECH / 4)) / 256; it++) {
            int idx = t + it * 256;
            int row = idx >> 5, c = (idx & 31) * 4;
            float4 v = *(const float4*)&gq[(q0 + row) * E_ + ec + c];
            *(float4*)&qS[row * QST + c] = v;
        }
        #pragma unroll
        for (int it = 0; it < (NR * (ECH / 4)) / 256; it++) {
            int idx = t + it * 256;
            int row = idx >> 5, c = (idx & 31) * 4;
            int kg = q0 - WIN + row;
            float4 v = make_float4(0.f, 0.f, 0.f, 0.f);
            if (kg >= 0 && kg < L_)
                v = *(const float4*)&gk[kg * E_ + ec + c];
            float* dst = &kvS[row * KST + c];
            dst[0] = v.x; dst[1] = v.y; dst[2] = v.z; dst[3] = v.w;
        }
        __syncthreads();

        #pragma unroll 4
        for (int e = 0; e < ECH; e++) {
            float a[4], kk[5];
            #pragma unroll
            for (int i = 0; i < 4; i++) a[i] = qS[(ty * 4 + i) * QST + e];
            #pragma unroll
            for (int j = 0; j < 5; j++) kk[j] = kvS[(tx + 32 * j) * KST + e];
            #pragma unroll
            for (int i = 0; i < 4; i++)
                #pragma unroll
                for (int j = 0; j < 5; j++)
                    acc[i][j] = fmaf(a[i], kk[j], acc[i][j]);
        }
        __syncthreads();
    }

    #pragma unroll
    for (int i = 0; i < 4; i++)
        #pragma unroll
        for (int j = 0; j < 5; j++)
            scS[(ty * 4 + i) * SST + tx + 32 * j] = acc[i][j];
    __syncthreads();

    // ---------- Softmax: 8 lanes per query, 20 elements per lane ------------
    {
        const float inv_sqrt_e = 0.04419417382415922f;  // 1/sqrt(512)
        const int qi  = t >> 3;
        const int sub = t & 7;
        float vals[20];
        float m = -INFINITY;
        #pragma unroll
        for (int u = 0; u < 20; u++) {
            int r  = sub * 20 + u;
            int wj = r - qi;
            int kg = q0 + r - WIN;
            bool valid = (wj >= 0) && (wj <= 2 * WIN) && (kg >= 0) && (kg < L_);
            float s = valid ? scS[qi * SST + r] * inv_sqrt_e : -INFINITY;
            vals[u] = s;
            m = fmaxf(m, s);
        }
        #pragma unroll
        for (int o = 1; o < 8; o <<= 1)
            m = fmaxf(m, __shfl_xor_sync(0xffffffffu, m, o, 8));
        float ssum = 0.f;
        #pragma unroll
        for (int u = 0; u < 20; u++) {
            float e = (vals[u] == -INFINITY) ? 0.f : __expf(vals[u] - m);
            vals[u] = e;
            ssum += e;
        }
        #pragma unroll
        for (int o = 1; o < 8; o <<= 1)
            ssum += __shfl_xor_sync(0xffffffffu, ssum, o, 8);
        float inv = 1.f / ssum;
        #pragma unroll
        for (int u = 0; u < 20; u++)
            scS[qi * SST + sub * 20 + u] = vals[u] * inv;
    }
    __syncthreads();

    // ---------- Phase 2: out = probs @ V, per E chunk ------------------------
    float* gout = out + b * (L_ * E_);
    for (int ec = 0; ec < E_; ec += ECH) {
        #pragma unroll
        for (int it = 0; it < (NR * (ECH / 4)) / 256; it++) {
            int idx = t + it * 256;
            int row = idx >> 5, c = (idx & 31) * 4;
            int kg = q0 - WIN + row;
            float4 v = make_float4(0.f, 0.f, 0.f, 0.f);
            if (kg >= 0 && kg < L_)
                v = *(const float4*)&gv[kg * E_ + ec + c];
            *(float4*)&kvS[row * VST + c] = v;
        }
        __syncthreads();

        float o[4][4];
        #pragma unroll
        for (int i = 0; i < 4; i++)
            #pragma unroll
            for (int j = 0; j < 4; j++) o[i][j] = 0.f;

        #pragma unroll 2
        for (int r = 0; r < NR; r++) {
            float4 vv = *(const float4*)&kvS[r * VST + tx * 4];
            float p[4];
            #pragma unroll
            for (int i = 0; i < 4; i++) p[i] = scS[(ty * 4 + i) * SST + r];
            #pragma unroll
            for (int i = 0; i < 4; i++) {
                o[i][0] = fmaf(p[i], vv.x, o[i][0]);
                o[i][1] = fmaf(p[i], vv.y, o[i][1]);
                o[i][2] = fmaf(p[i], vv.z, o[i][2]);
                o[i][3] = fmaf(p[i], vv.w, o[i][3]);
            }
        }

        #pragma unroll
        for (int i = 0; i < 4; i++) {
            float4 w;
            w.x = o[i][0]; w.y = o[i][1]; w.z = o[i][2]; w.w = o[i][3];
            *(float4*)&gout[(q0 + ty * 4 + i) * E_ + ec + tx * 4] = w;
        }
        __syncthreads();
    }
}

// ============================================================================
extern "C" void kernel_launch(void* const* d_in, const int* in_sizes, int n_in,
                              void* d_out, int out_size)
{
    const float* x  = (const float*)d_in[0];
    const float* Wq = (const float*)d_in[1];
    const float* bq = (const float*)d_in[2];
    const float* Wk = (const float*)d_in[3];
    const float* bk = (const float*)d_in[4];
    const float* Wv = (const float*)d_in[5];
    const float* bv = (const float*)d_in[6];
    float* out = (float*)d_out;

    // QKV projections on tensor cores: grid (M/128, N/128, 3)
    cudaFuncSetAttribute(qkv_tc, cudaFuncAttributeMaxDynamicSharedMemorySize,
                         QT_SMEM);
    dim3 ggrid((B_ * L_) / 128, E_ / 128, 3);
    qkv_tc<<<ggrid, 256, QT_SMEM>>>(x, Wq, bq, Wk, bk, Wv, bv);

    // Attention: 122.6 KB dynamic smem
    static const size_t smem_bytes = SMEM_FLOATS * sizeof(float);
    cudaFuncSetAttribute(local_attn, cudaFuncAttributeMaxDynamicSharedMemorySize,
                         (int)smem_bytes);
    dim3 agrid(L_ / TQ, B_);
    local_attn<<<agrid, 256, smem_bytes>>>(out);
}

// round 11
// speedup vs baseline: 2.1275x; 1.2110x over previous
#include <cuda_runtime.h>
#include <cuda_bf16.h>
#include <math.h>
#include <stdint.h>

// Problem shapes (fixed by setup_inputs): B=2, L=2048, E=512, window=64
#define B_  2
#define L_  2048
#define E_  512
#define WIN 64

// ---------------- scratch (device globals; no cudaMalloc allowed) ----------
// split-precision bf16 pairs: value ~= hi + lo (residual ~2^-16 relative)
__device__ __nv_bfloat16 g_xhi[B_ * L_ * E_], g_xlo[B_ * L_ * E_];
__device__ __nv_bfloat16 g_whi[3 * E_ * E_], g_wlo[3 * E_ * E_];
__device__ __nv_bfloat16 g_qhi[B_ * L_ * E_], g_qlo[B_ * L_ * E_];
__device__ __nv_bfloat16 g_khi[B_ * L_ * E_], g_klo[B_ * L_ * E_];
__device__ __nv_bfloat16 g_vhi[B_ * L_ * E_], g_vlo[B_ * L_ * E_];

// ============================================================================
// Warp-level tensor-core primitives (baseline PTX; harness targets compute_103)
// ============================================================================
static __device__ __forceinline__ uint32_t smem_u32(const void* p) {
    uint32_t a;
    asm("{ .reg .u64 t; cvta.to.shared.u64 t, %1; cvt.u32.u64 %0, t; }"
        : "=r"(a) : "l"(p));
    return a;
}

static __device__ __forceinline__ void ldsm_x4(uint32_t (&r)[4], uint32_t addr)
{
    asm volatile("ldmatrix.sync.aligned.m8n8.x4.shared.b16 {%0,%1,%2,%3}, [%4];"
        : "=r"(r[0]), "=r"(r[1]), "=r"(r[2]), "=r"(r[3]) : "r"(addr));
}

static __device__ __forceinline__ void ldsm_x4_t(uint32_t (&r)[4], uint32_t addr)
{
    asm volatile("ldmatrix.sync.aligned.m8n8.x4.trans.shared.b16 {%0,%1,%2,%3}, [%4];"
        : "=r"(r[0]), "=r"(r[1]), "=r"(r[2]), "=r"(r[3]) : "r"(addr));
}

static __device__ __forceinline__ void mma16816(
    float (&c)[4], const uint32_t (&a)[4], uint32_t b0, uint32_t b1)
{
    asm volatile(
        "mma.sync.aligned.m16n8k16.row.col.f32.bf16.bf16.f32 "
        "{%0,%1,%2,%3}, {%4,%5,%6,%7}, {%8,%9}, {%0,%1,%2,%3};"
        : "+f"(c[0]), "+f"(c[1]), "+f"(c[2]), "+f"(c[3])
        : "r"(a[0]), "r"(a[1]), "r"(a[2]), "r"(a[3]), "r"(b0), "r"(b1));
}

// fp32 -> (bf16 hi, bf16 lo) split, 4-wide
static __device__ __forceinline__ void cvt_split(float4 f, uint2& hi, uint2& lo)
{
    float v[4] = {f.x, f.y, f.z, f.w};
    unsigned short h[4], l[4];
#pragma unroll
    for (int i = 0; i < 4; i++) {
        __nv_bfloat16 hb = __float2bfloat16(v[i]);
        float r = v[i] - __bfloat162float(hb);
        __nv_bfloat16 lb = __float2bfloat16(r);
        h[i] = __bfloat16_as_ushort(hb);
        l[i] = __bfloat16_as_ushort(lb);
    }
    hi.x = (uint32_t)h[0] | ((uint32_t)h[1] << 16);
    hi.y = (uint32_t)h[2] | ((uint32_t)h[3] << 16);
    lo.x = (uint32_t)l[0] | ((uint32_t)l[1] << 16);
    lo.y = (uint32_t)l[2] | ((uint32_t)l[3] << 16);
}

static __device__ __forceinline__ void split2_store(
    __nv_bfloat16* hi, __nv_bfloat16* lo, size_t off, float a, float b)
{
    __nv_bfloat16 ha = __float2bfloat16(a), hb = __float2bfloat16(b);
    __nv_bfloat16 la = __float2bfloat16(a - __bfloat162float(ha));
    __nv_bfloat16 lb = __float2bfloat16(b - __bfloat162float(hb));
    *(__nv_bfloat162*)(hi + off) = __halves2bfloat162(ha, hb);
    *(__nv_bfloat162*)(lo + off) = __halves2bfloat162(la, lb);
}

// ============================================================================
// Pre-pass: split fp32 X / Wq / Wk / Wv into bf16 hi/lo global arrays.
// grid = (512, 4); blockIdx.y selects the tensor; grid-stride over float4s.
// ============================================================================
__global__ __launch_bounds__(256) void split_all(
    const float* __restrict__ X,  const float* __restrict__ Wq,
    const float* __restrict__ Wk, const float* __restrict__ Wv)
{
    const float* src; __nv_bfloat16 *hi, *lo; int n4;
    switch (blockIdx.y) {
        case 0:  src = X;  hi = g_xhi;              lo = g_xlo;              n4 = (B_*L_*E_)/4; break;
        case 1:  src = Wq; hi = g_whi;              lo = g_wlo;              n4 = (E_*E_)/4;    break;
        case 2:  src = Wk; hi = g_whi + E_*E_;      lo = g_wlo + E_*E_;      n4 = (E_*E_)/4;    break;
        default: src = Wv; hi = g_whi + 2*E_*E_;    lo = g_wlo + 2*E_*E_;    n4 = (E_*E_)/4;    break;
    }
    for (int i = blockIdx.x * blockDim.x + threadIdx.x; i < n4;
         i += gridDim.x * blockDim.x) {
        float4 v = ((const float4*)src)[i];
        uint2 h, l; cvt_split(v, h, l);
        ((uint2*)hi)[i] = h;
        ((uint2*)lo)[i] = l;
    }
}

// ============================================================================
// QKV GEMM on tensor cores (bf16 split inputs, fp32 accum, split bf16 output).
// C = X @ W^T + bias; M=4096, N=512, K=512. CTA 128x128, K chunks of 64.
// Smem: A_hi/A_lo/B_hi/B_lo bf16 tiles, row stride 72 bf16 (144 B).
// 8 warps = 2(M) x 4(N); splits Ahi*Bhi + Ahi*Blo + Alo*Bhi.
// Epilogue: bias add in fp32, then split-store q/k/v as bf16 hi/lo pairs.
// ============================================================================
#define STRH  72                      // smem row stride (bf16 units)
#define TILEB (128 * STRH * 2)        // 18432 bytes per tile
#define QT_SMEM (4 * TILEB)           // 73728 bytes

__global__ __launch_bounds__(256) void qkv_tc(
    const float* __restrict__ b0p, const float* __restrict__ b1p,
    const float* __restrict__ b2p)
{
    extern __shared__ __align__(16) char smem[];
    const uint32_t sb = smem_u32(smem);

    const int z = blockIdx.z;
    const __nv_bfloat16* Whi = g_whi + (size_t)z * E_ * E_;
    const __nv_bfloat16* Wlo = g_wlo + (size_t)z * E_ * E_;
    __nv_bfloat16 *Chi, *Clo; const float* bias;
    if (z == 0)      { Chi = g_qhi; Clo = g_qlo; bias = b0p; }
    else if (z == 1) { Chi = g_khi; Clo = g_klo; bias = b1p; }
    else             { Chi = g_vhi; Clo = g_vlo; bias = b2p; }

    const int m0  = blockIdx.x * 128;
    const int n0  = blockIdx.y * 128;
    const int t   = threadIdx.x;
    const int wid = t >> 5;
    const int lid = t & 31;
    const int wm  = wid & 1;
    const int wn  = wid >> 1;

    float acc[4][4][4];
#pragma unroll
    for (int mi = 0; mi < 4; mi++)
#pragma unroll
        for (int ni = 0; ni < 4; ni++)
#pragma unroll
            for (int r = 0; r < 4; r++) acc[mi][ni][r] = 0.f;

    const int g = lid >> 3, r8 = lid & 7;
    const uint32_t aLaneOff = (uint32_t)((((g & 1) * 8 + r8) * STRH + (g >> 1) * 8) * 2);
    const uint32_t bLaneOff = (uint32_t)((((g >> 1) * 8 + r8) * STRH + (g & 1) * 8) * 2);

    for (int ck = 0; ck < 8; ck++) {
        const int k0 = ck * 64;
        // load 4 bf16 tiles (128 x 64 each): 1024 uint4 per tile, 4 iters
#pragma unroll
        for (int it = 0; it < 4; it++) {
            int idx = t + it * 256;
            int row = idx >> 3, c8 = idx & 7;
            uint32_t off = (uint32_t)(row * (STRH * 2) + c8 * 16);
            *(uint4*)(smem + off) =
                *(const uint4*)&g_xhi[(size_t)(m0 + row) * E_ + k0 + c8 * 8];
            *(uint4*)(smem + TILEB + off) =
                *(const uint4*)&g_xlo[(size_t)(m0 + row) * E_ + k0 + c8 * 8];
            *(uint4*)(smem + 2 * TILEB + off) =
                *(const uint4*)&Whi[(size_t)(n0 + row) * E_ + k0 + c8 * 8];
            *(uint4*)(smem + 3 * TILEB + off) =
                *(const uint4*)&Wlo[(size_t)(n0 + row) * E_ + k0 + c8 * 8];
        }
        __syncthreads();

#pragma unroll
        for (int kk = 0; kk < 4; kk++) {
            const uint32_t kOff = (uint32_t)(kk * 32);
            uint32_t aH[4][4], aL[4][4], bH[2][4], bL[2][4];
#pragma unroll
            for (int mi = 0; mi < 4; mi++) {
                uint32_t rowOff = (uint32_t)((wm * 64 + mi * 16) * (STRH * 2));
                ldsm_x4(aH[mi], sb + rowOff + kOff + aLaneOff);
                ldsm_x4(aL[mi], sb + TILEB + rowOff + kOff + aLaneOff);
            }
#pragma unroll
            for (int nj = 0; nj < 2; nj++) {
                uint32_t rowOff = (uint32_t)((wn * 32 + nj * 16) * (STRH * 2));
                ldsm_x4(bH[nj], sb + 2 * TILEB + rowOff + kOff + bLaneOff);
                ldsm_x4(bL[nj], sb + 3 * TILEB + rowOff + kOff + bLaneOff);
            }
#pragma unroll
            for (int mi = 0; mi < 4; mi++)
#pragma unroll
                for (int ni = 0; ni < 4; ni++) {
                    uint32_t h0 = bH[ni >> 1][(ni & 1) * 2];
                    uint32_t h1 = bH[ni >> 1][(ni & 1) * 2 + 1];
                    uint32_t l0 = bL[ni >> 1][(ni & 1) * 2];
                    uint32_t l1 = bL[ni >> 1][(ni & 1) * 2 + 1];
                    mma16816(acc[mi][ni], aH[mi], h0, h1);   // hi*hi
                    mma16816(acc[mi][ni], aH[mi], l0, l1);   // hi*lo
                    mma16816(acc[mi][ni], aL[mi], h0, h1);   // lo*hi
                }
        }
        __syncthreads();
    }

    // epilogue: bias add (fp32), split-store to hi/lo bf16 outputs
    const int qg = lid >> 2;
    const int qi = lid & 3;
#pragma unroll
    for (int ni = 0; ni < 4; ni++) {
        int col = n0 + wn * 32 + ni * 8 + qi * 2;
        float2 bb = *(const float2*)&bias[col];
#pragma unroll
        for (int mi = 0; mi < 4; mi++) {
            int row = m0 + wm * 64 + mi * 16 + qg;
            split2_store(Chi, Clo, (size_t)row * E_ + col,
                         acc[mi][ni][0] + bb.x, acc[mi][ni][1] + bb.y);
            split2_store(Chi, Clo, (size_t)(row + 8) * E_ + col,
                         acc[mi][ni][2] + bb.x, acc[mi][ni][3] + bb.y);
        }
    }
}

// ============================================================================
// Banded local attention, fully on tensor cores.
// Block = 32 queries. Key rows [q0-64, q0+95] -> 160, padded to 192.
// Phase 1: S[32][192] = Q @ K^T (split bf16, 8 e-chunks of 64).
//   Warp w: 2 m16 x 3 n8 tiles at n = w*24.. (extra rows discarded).
// Softmax: fp32 via smem (unchanged), writes P as split bf16 hi/lo.
// Phase 2: out[32][512] = P[32][192] @ V; per e-chunk of 64, warp w owns one
//   n8 column (e = w*8..w*8+7); V^T fragments via ldmatrix.x4.trans.
// ============================================================================
#define TQ   32
#define NR   160
#define NRP  192
#define ACH  64
#define PSTR 200          // P smem stride (bf16): 400 B -> 4-bank row step
#define SSTA 161          // scores fp32 stride

#define O_QHI 0
#define O_QLO (O_QHI + TQ * STRH * 2)        // 4608
#define O_KHI (O_QLO + TQ * STRH * 2)        // 9216
#define O_KLO (O_KHI + NRP * STRH * 2)       // 36864
#define O_SC  (O_KLO + NRP * STRH * 2)       // 64512
#define O_PHI (O_SC  + TQ * SSTA * 4)        // 85120
#define O_PLO (O_PHI + TQ * PSTR * 2)        // 97920
#define A_SMEM (O_PLO + TQ * PSTR * 2)       // 110720 bytes

__global__ __launch_bounds__(256) void attn_tc(float* __restrict__ out)
{
    extern __shared__ __align__(16) char smem[];
    const uint32_t sb = smem_u32(smem);
    float* scS = (float*)(smem + O_SC);

    const int q0  = blockIdx.x * TQ;
    const int b   = blockIdx.y;
    const int t   = threadIdx.x;
    const int wid = t >> 5;
    const int lid = t & 31;
    const int g   = lid >> 3, r8 = lid & 7;
    const size_t base = (size_t)b * (L_ * E_);

    const uint32_t aOff  = (uint32_t)((((g & 1) * 8 + r8) * STRH + (g >> 1) * 8) * 2);
    const uint32_t bOff  = (uint32_t)((((g >> 1) * 8 + r8) * STRH + (g & 1) * 8) * 2);
    const uint32_t aPOff = (uint32_t)((((g & 1) * 8 + r8) * PSTR + (g >> 1) * 8) * 2);

    // ---------------- Phase 1: S = Q K^T -----------------------------------
    float acc[2][3][4];
#pragma unroll
    for (int mi = 0; mi < 2; mi++)
#pragma unroll
        for (int nj = 0; nj < 3; nj++)
#pragma unroll
            for (int r = 0; r < 4; r++) acc[mi][nj][r] = 0.f;

    for (int ec = 0; ec < E_; ec += ACH) {
        {   // Q tile 32x64: 256 uint4 per array, 1 per thread
            int row = t >> 3, c8 = t & 7;
            uint32_t off = (uint32_t)(row * (STRH * 2) + c8 * 16);
            size_t gidx = base + (size_t)(q0 + row) * E_ + ec + c8 * 8;
            *(uint4*)(smem + O_QHI + off) = *(const uint4*)&g_qhi[gidx];
            *(uint4*)(smem + O_QLO + off) = *(const uint4*)&g_qlo[gidx];
        }
        // K rows 0..159 (guarded), 1280 uint4 per array: 5 iters
#pragma unroll
        for (int it = 0; it < 5; it++) {
            int idx = t + it * 256;
            int row = idx >> 3, c8 = idx & 7;
            int kg  = q0 - WIN + row;
            uint32_t off = (uint32_t)(row * (STRH * 2) + c8 * 16);
            uint4 h = make_uint4(0, 0, 0, 0), l = make_uint4(0, 0, 0, 0);
            if (kg >= 0 && kg < L_) {
                size_t gidx = base + (size_t)kg * E_ + ec + c8 * 8;
                h = *(const uint4*)&g_khi[gidx];
                l = *(const uint4*)&g_klo[gidx];
            }
            *(uint4*)(smem + O_KHI + off) = h;
            *(uint4*)(smem + O_KLO + off) = l;
        }
        __syncthreads();

#pragma unroll
        for (int kk = 0; kk < 4; kk++) {
            const uint32_t kOff = (uint32_t)(kk * 32);
            uint32_t aH[2][4], aL[2][4];
#pragma unroll
            for (int mi = 0; mi < 2; mi++) {
                uint32_t rowOff = (uint32_t)(mi * 16 * (STRH * 2));
                ldsm_x4(aH[mi], sb + O_QHI + rowOff + kOff + aOff);
                ldsm_x4(aL[mi], sb + O_QLO + rowOff + kOff + aOff);
            }
            const uint32_t nb0 = (uint32_t)(wid * 24 * (STRH * 2));
            const uint32_t nb1 = (uint32_t)((wid * 24 + 16) * (STRH * 2));
            uint32_t bH0[4], bH1[4], bL0[4], bL1[4];
            ldsm_x4(bH0, sb + O_KHI + nb0 + kOff + bOff);
            ldsm_x4(bH1, sb + O_KHI + nb1 + kOff + bOff);
            ldsm_x4(bL0, sb + O_KLO + nb0 + kOff + bOff);
            ldsm_x4(bL1, sb + O_KLO + nb1 + kOff + bOff);
#pragma unroll
            for (int mi = 0; mi < 2; mi++)
#pragma unroll
                for (int nj = 0; nj < 3; nj++) {
                    uint32_t h0 = (nj < 2) ? bH0[nj * 2]     : bH1[0];
                    uint32_t h1 = (nj < 2) ? bH0[nj * 2 + 1] : bH1[1];
                    uint32_t l0 = (nj < 2) ? bL0[nj * 2]     : bL1[0];
                    uint32_t l1 = (nj < 2) ? bL0[nj * 2 + 1] : bL1[1];
                    mma16816(acc[mi][nj], aH[mi], h0, h1);
                    mma16816(acc[mi][nj], aH[mi], l0, l1);
                    mma16816(acc[mi][nj], aL[mi], h0, h1);
                }
        }
        __syncthreads();
    }

    // write scores (n < 160 only) to fp32 smem
    {
        const int rA = lid >> 2, cA = (lid & 3) * 2;
#pragma unroll
        for (int mi = 0; mi < 2; mi++)
#pragma unroll
            for (int nj = 0; nj < 3; nj++) {
                int n = wid * 24 + nj * 8 + cA;
                if (n < NR) {
                    int r0 = mi * 16 + rA;
                    scS[r0 * SSTA + n]           = acc[mi][nj][0];
                    scS[r0 * SSTA + n + 1]       = acc[mi][nj][1];
                    scS[(r0 + 8) * SSTA + n]     = acc[mi][nj][2];
                    scS[(r0 + 8) * SSTA + n + 1] = acc[mi][nj][3];
                }
            }
    }
    __syncthreads();

    // ---------------- Softmax (fp32), emit P as split bf16 ------------------
    {
        const float inv_sqrt_e = 0.04419417382415922f;  // 1/sqrt(512)
        const int qi  = t >> 3;
        const int sub = t & 7;
        float vals[20];
        float m = -INFINITY;
#pragma unroll
        for (int u = 0; u < 20; u++) {
            int r  = sub * 20 + u;
            int wj = r - qi;
            int kg = q0 + r - WIN;
            bool valid = (wj >= 0) && (wj <= 2 * WIN) && (kg >= 0) && (kg < L_);
            float s = valid ? scS[qi * SSTA + r] * inv_sqrt_e : -INFINITY;
            vals[u] = s;
            m = fmaxf(m, s);
        }
#pragma unroll
        for (int o = 1; o < 8; o <<= 1)
            m = fmaxf(m, __shfl_xor_sync(0xffffffffu, m, o, 8));
        float ssum = 0.f;
#pragma unroll
        for (int u = 0; u < 20; u++) {
            float e = (vals[u] == -INFINITY) ? 0.f : __expf(vals[u] - m);
            vals[u] = e;
            ssum += e;
        }
#pragma unroll
        for (int o = 1; o < 8; o <<= 1)
            ssum += __shfl_xor_sync(0xffffffffu, ssum, o, 8);
        float inv = 1.f / ssum;

        __nv_bfloat16* phi = (__nv_bfloat16*)(smem + O_PHI);
        __nv_bfloat16* plo = (__nv_bfloat16*)(smem + O_PLO);
#pragma unroll
        for (int u = 0; u < 20; u++) {
            float p = vals[u] * inv;
            __nv_bfloat16 h = __float2bfloat16(p);
            __nv_bfloat16 l = __float2bfloat16(p - __bfloat162float(h));
            phi[qi * PSTR + sub * 20 + u] = h;
            plo[qi * PSTR + sub * 20 + u] = l;
        }
        // zero pad columns 160..191 (k-dim padding for phase 2)
        __nv_bfloat16 z = __float2bfloat16(0.0f);
#pragma unroll
        for (int u = 0; u < 4; u++) {
            int r = NR + sub * 4 + u;
            phi[qi * PSTR + r] = z;
            plo[qi * PSTR + r] = z;
        }
    }
    __syncthreads();

    // ---------------- Phase 2: out = P @ V ---------------------------------
    float* gout = out + base;
    for (int ec = 0; ec < E_; ec += ACH) {
        // V rows 0..159 (guarded, zero OOB)
#pragma unroll
        for (int it = 0; it < 5; it++) {
            int idx = t + it * 256;
            int row = idx >> 3, c8 = idx & 7;
            int kg  = q0 - WIN + row;
            uint32_t off = (uint32_t)(row * (STRH * 2) + c8 * 16);
            uint4 h = make_uint4(0, 0, 0, 0), l = make_uint4(0, 0, 0, 0);
            if (kg >= 0 && kg < L_) {
                size_t gidx = base + (size_t)kg * E_ + ec + c8 * 8;
                h = *(const uint4*)&g_vhi[gidx];
                l = *(const uint4*)&g_vlo[gidx];
            }
            *(uint4*)(smem + O_KHI + off) = h;
            *(uint4*)(smem + O_KLO + off) = l;
        }
        {   // zero pad rows 160..191 (avoid 0 x NaN in discarded k range)
            int row = NR + (t >> 3), c8 = t & 7;
            uint32_t off = (uint32_t)(row * (STRH * 2) + c8 * 16);
            uint4 zz = make_uint4(0, 0, 0, 0);
            *(uint4*)(smem + O_KHI + off) = zz;
            *(uint4*)(smem + O_KLO + off) = zz;
        }
        __syncthreads();

        float o[2][4];
#pragma unroll
        for (int mi = 0; mi < 2; mi++)
#pragma unroll
            for (int r = 0; r < 4; r++) o[mi][r] = 0.f;

#pragma unroll
        for (int ks = 0; ks < 6; ks++) {   // k32 per iteration (192 total)
            // V^T fragments: 32 lanes -> rows ks*32+lid, col = warp's 8 e-vals
            uint32_t vrow = (uint32_t)((ks * 32 + lid) * (STRH * 2) + wid * 16);
            uint32_t vH[4], vL[4];
            ldsm_x4_t(vH, sb + O_KHI + vrow);
            ldsm_x4_t(vL, sb + O_KLO + vrow);
#pragma unroll
            for (int half = 0; half < 2; half++) {
                uint32_t kOff = (uint32_t)((ks * 32 + half * 16) * 2);
                uint32_t aH[2][4], aL[2][4];
#pragma unroll
                for (int mi = 0; mi < 2; mi++) {
                    uint32_t rowOff = (uint32_t)(mi * 16 * (PSTR * 2));
                    ldsm_x4(aH[mi], sb + O_PHI + rowOff + kOff + aPOff);
                    ldsm_x4(aL[mi], sb + O_PLO + rowOff + kOff + aPOff);
                }
                uint32_t h0 = vH[half * 2], h1 = vH[half * 2 + 1];
                uint32_t l0 = vL[half * 2], l1 = vL[half * 2 + 1];
#pragma unroll
                for (int mi = 0; mi < 2; mi++) {
                    mma16816(o[mi], aH[mi], h0, h1);   // Phi*Vhi
                    mma16816(o[mi], aH[mi], l0, l1);   // Phi*Vlo
                    mma16816(o[mi], aL[mi], h0, h1);   // Plo*Vhi
                }
            }
        }

        {   // store fp32 output
            int col = ec + wid * 8 + (lid & 3) * 2;
#pragma unroll
            for (int mi = 0; mi < 2; mi++) {
                int r = q0 + mi * 16 + (lid >> 2);
                *(float2*)&gout[(size_t)r * E_ + col] =
                    make_float2(o[mi][0], o[mi][1]);
                *(float2*)&gout[(size_t)(r + 8) * E_ + col] =
                    make_float2(o[mi][2], o[mi][3]);
            }
        }
        __syncthreads();
    }
}

// ============================================================================
extern "C" void kernel_launch(void* const* d_in, const int* in_sizes, int n_in,
                              void* d_out, int out_size)
{
    const float* x  = (const float*)d_in[0];
    const float* Wq = (const float*)d_in[1];
    const float* bq = (const float*)d_in[2];
    const float* Wk = (const float*)d_in[3];
    const float* bk = (const float*)d_in[4];
    const float* Wv = (const float*)d_in[5];
    const float* bv = (const float*)d_in[6];
    float* out = (float*)d_out;

    // 1) split X / W into bf16 hi/lo
    split_all<<<dim3(512, 4), 256>>>(x, Wq, Wk, Wv);

    // 2) QKV projections on tensor cores -> split bf16 q/k/v
    cudaFuncSetAttribute(qkv_tc, cudaFuncAttributeMaxDynamicSharedMemorySize,
                         QT_SMEM);
    dim3 ggrid((B_ * L_) / 128, E_ / 128, 3);
    qkv_tc<<<ggrid, 256, QT_SMEM>>>(bq, bk, bv);

    // 3) banded attention on tensor cores
    cudaFuncSetAttribute(attn_tc, cudaFuncAttributeMaxDynamicSharedMemorySize,
                         A_SMEM);
    dim3 agrid(L_ / TQ, B_);
    attn_tc<<<agrid, 256, A_SMEM>>>(out);
}

// round 13
// speedup vs baseline: 2.2083x; 1.0380x over previous
#include <cuda_runtime.h>
#include <cuda_bf16.h>
#include <math.h>
#include <stdint.h>

// Problem shapes (fixed by setup_inputs): B=2, L=2048, E=512, window=64
#define B_  2
#define L_  2048
#define E_  512
#define WIN 64

// ---------------- scratch (device globals; no cudaMalloc allowed) ----------
// split-precision bf16 pairs: value ~= hi + lo (residual ~2^-16 relative)
__device__ __nv_bfloat16 g_xhi[B_ * L_ * E_], g_xlo[B_ * L_ * E_];
__device__ __nv_bfloat16 g_whi[3 * E_ * E_], g_wlo[3 * E_ * E_];
__device__ __nv_bfloat16 g_qhi[B_ * L_ * E_], g_qlo[B_ * L_ * E_];
__device__ __nv_bfloat16 g_khi[B_ * L_ * E_], g_klo[B_ * L_ * E_];
__device__ __nv_bfloat16 g_vhi[B_ * L_ * E_], g_vlo[B_ * L_ * E_];

// ============================================================================
// Warp-level tensor-core + async-copy primitives (baseline PTX, compute_103)
// ============================================================================
static __device__ __forceinline__ uint32_t smem_u32(const void* p) {
    uint32_t a;
    asm("{ .reg .u64 t; cvta.to.shared.u64 t, %1; cvt.u32.u64 %0, t; }"
        : "=r"(a) : "l"(p));
    return a;
}

static __device__ __forceinline__ void ldsm_x4(uint32_t (&r)[4], uint32_t addr)
{
    asm volatile("ldmatrix.sync.aligned.m8n8.x4.shared.b16 {%0,%1,%2,%3}, [%4];"
        : "=r"(r[0]), "=r"(r[1]), "=r"(r[2]), "=r"(r[3]) : "r"(addr));
}

static __device__ __forceinline__ void ldsm_x4_t(uint32_t (&r)[4], uint32_t addr)
{
    asm volatile("ldmatrix.sync.aligned.m8n8.x4.trans.shared.b16 {%0,%1,%2,%3}, [%4];"
        : "=r"(r[0]), "=r"(r[1]), "=r"(r[2]), "=r"(r[3]) : "r"(addr));
}

static __device__ __forceinline__ void mma16816(
    float (&c)[4], const uint32_t (&a)[4], uint32_t b0, uint32_t b1)
{
    asm volatile(
        "mma.sync.aligned.m16n8k16.row.col.f32.bf16.bf16.f32 "
        "{%0,%1,%2,%3}, {%4,%5,%6,%7}, {%8,%9}, {%0,%1,%2,%3};"
        : "+f"(c[0]), "+f"(c[1]), "+f"(c[2]), "+f"(c[3])
        : "r"(a[0]), "r"(a[1]), "r"(a[2]), "r"(a[3]), "r"(b0), "r"(b1));
}

// 16B global->shared async copy
static __device__ __forceinline__ void cp16(uint32_t dst, const void* src)
{
    asm volatile("cp.async.cg.shared.global [%0], [%1], 16;"
        :: "r"(dst), "l"(src));
}
// predicated: pred==false -> zero-fill 16B (src must still be a valid address)
static __device__ __forceinline__ void cp16z(uint32_t dst, const void* src, bool pred)
{
    int sz = pred ? 16 : 0;
    asm volatile("cp.async.cg.shared.global [%0], [%1], 16, %2;"
        :: "r"(dst), "l"(src), "r"(sz));
}
#define CP_COMMIT() asm volatile("cp.async.commit_group;" ::: "memory")
#define CP_WAIT(n)  asm volatile("cp.async.wait_group %0;" :: "n"(n) : "memory")

// fp32 -> (bf16 hi, bf16 lo) split, 4-wide
static __device__ __forceinline__ void cvt_split(float4 f, uint2& hi, uint2& lo)
{
    float v[4] = {f.x, f.y, f.z, f.w};
    unsigned short h[4], l[4];
#pragma unroll
    for (int i = 0; i < 4; i++) {
        __nv_bfloat16 hb = __float2bfloat16(v[i]);
        float r = v[i] - __bfloat162float(hb);
        __nv_bfloat16 lb = __float2bfloat16(r);
        h[i] = __bfloat16_as_ushort(hb);
        l[i] = __bfloat16_as_ushort(lb);
    }
    hi.x = (uint32_t)h[0] | ((uint32_t)h[1] << 16);
    hi.y = (uint32_t)h[2] | ((uint32_t)h[3] << 16);
    lo.x = (uint32_t)l[0] | ((uint32_t)l[1] << 16);
    lo.y = (uint32_t)l[2] | ((uint32_t)l[3] << 16);
}

static __device__ __forceinline__ void split2_store(
    __nv_bfloat16* hi, __nv_bfloat16* lo, size_t off, float a, float b)
{
    __nv_bfloat16 ha = __float2bfloat16(a), hb = __float2bfloat16(b);
    __nv_bfloat16 la = __float2bfloat16(a - __bfloat162float(ha));
    __nv_bfloat16 lb = __float2bfloat16(b - __bfloat162float(hb));
    *(__nv_bfloat162*)(hi + off) = __halves2bfloat162(ha, hb);
    *(__nv_bfloat162*)(lo + off) = __halves2bfloat162(la, lb);
}

// ============================================================================
// Pre-pass: split fp32 X / Wq / Wk / Wv into bf16 hi/lo global arrays.
// ============================================================================
__global__ __launch_bounds__(256) void split_all(
    const float* __restrict__ X,  const float* __restrict__ Wq,
    const float* __restrict__ Wk, const float* __restrict__ Wv)
{
    const float* src; __nv_bfloat16 *hi, *lo; int n4;
    switch (blockIdx.y) {
        case 0:  src = X;  hi = g_xhi;           lo = g_xlo;           n4 = (B_*L_*E_)/4; break;
        case 1:  src = Wq; hi = g_whi;           lo = g_wlo;           n4 = (E_*E_)/4;    break;
        case 2:  src = Wk; hi = g_whi + E_*E_;   lo = g_wlo + E_*E_;   n4 = (E_*E_)/4;    break;
        default: src = Wv; hi = g_whi + 2*E_*E_; lo = g_wlo + 2*E_*E_; n4 = (E_*E_)/4;    break;
    }
    for (int i = blockIdx.x * blockDim.x + threadIdx.x; i < n4;
         i += gridDim.x * blockDim.x) {
        float4 v = ((const float4*)src)[i];
        uint2 h, l; cvt_split(v, h, l);
        ((uint2*)hi)[i] = h;
        ((uint2*)lo)[i] = l;
    }
}

// ============================================================================
// QKV GEMM on tensor cores, cp.async double-buffered pipeline.
// C = X @ W^T + bias; M=4096, N=512, K=512. CTA 128x128, K chunks of 64.
// Per stage: A_hi/A_lo/B_hi/B_lo bf16 tiles (128 x 64, row stride 72 bf16).
// 8 warps = 2(M) x 4(N); splits Ahi*Bhi + Ahi*Blo + Alo*Bhi.
// ============================================================================
#define STRH  72                      // smem row stride (bf16 units)
#define TILEB (128 * STRH * 2)        // 18432 bytes per tile
#define QSTG  (4 * TILEB)             // 73728 bytes per stage
#define QT_SMEM (2 * QSTG)            // 147456 bytes

__global__ __launch_bounds__(256) void qkv_tc(
    const float* __restrict__ b0p, const float* __restrict__ b1p,
    const float* __restrict__ b2p)
{
    extern __shared__ __align__(16) char smem[];
    const uint32_t sb = smem_u32(smem);

    const int z = blockIdx.z;
    const __nv_bfloat16* Whi = g_whi + (size_t)z * E_ * E_;
    const __nv_bfloat16* Wlo = g_wlo + (size_t)z * E_ * E_;
    __nv_bfloat16 *Chi, *Clo; const float* bias;
    if (z == 0)      { Chi = g_qhi; Clo = g_qlo; bias = b0p; }
    else if (z == 1) { Chi = g_khi; Clo = g_klo; bias = b1p; }
    else             { Chi = g_vhi; Clo = g_vlo; bias = b2p; }

    const int m0  = blockIdx.x * 128;
    const int n0  = blockIdx.y * 128;
    const int t   = threadIdx.x;
    const int wid = t >> 5;
    const int lid = t & 31;
    const int wm  = wid & 1;
    const int wn  = wid >> 1;

    float acc[4][4][4];
#pragma unroll
    for (int mi = 0; mi < 4; mi++)
#pragma unroll
        for (int ni = 0; ni < 4; ni++)
#pragma unroll
            for (int r = 0; r < 4; r++) acc[mi][ni][r] = 0.f;

    const int g = lid >> 3, r8 = lid & 7;
    const uint32_t aLaneOff = (uint32_t)((((g & 1) * 8 + r8) * STRH + (g >> 1) * 8) * 2);
    const uint32_t bLaneOff = (uint32_t)((((g >> 1) * 8 + r8) * STRH + (g & 1) * 8) * 2);

    // async load of one K-chunk (4 tiles) into stage buf
    auto load_chunk = [&](int ck, int buf) {
        const int k0 = ck * 64;
        const uint32_t bpa = sb + (uint32_t)buf * QSTG;
#pragma unroll
        for (int it = 0; it < 4; it++) {
            int idx = t + it * 256;
            int row = idx >> 3, c8 = idx & 7;
            uint32_t off = (uint32_t)(row * (STRH * 2) + c8 * 16);
            size_t ax = (size_t)(m0 + row) * E_ + k0 + c8 * 8;
            size_t bx = (size_t)(n0 + row) * E_ + k0 + c8 * 8;
            cp16(bpa + off,             g_xhi + ax);
            cp16(bpa + TILEB + off,     g_xlo + ax);
            cp16(bpa + 2 * TILEB + off, Whi + bx);
            cp16(bpa + 3 * TILEB + off, Wlo + bx);
        }
    };

    load_chunk(0, 0);
    CP_COMMIT();

    for (int ck = 0; ck < 8; ck++) {
        const int buf = ck & 1;
        if (ck < 7) {
            load_chunk(ck + 1, buf ^ 1);
            CP_COMMIT();
            CP_WAIT(1);
        } else {
            CP_WAIT(0);
        }
        __syncthreads();

        const uint32_t bp = sb + (uint32_t)buf * QSTG;
#pragma unroll
        for (int kk = 0; kk < 4; kk++) {
            const uint32_t kOff = (uint32_t)(kk * 32);
            uint32_t aH[4][4], aL[4][4], bH[2][4], bL[2][4];
#pragma unroll
            for (int mi = 0; mi < 4; mi++) {
                uint32_t rowOff = (uint32_t)((wm * 64 + mi * 16) * (STRH * 2));
                ldsm_x4(aH[mi], bp + rowOff + kOff + aLaneOff);
                ldsm_x4(aL[mi], bp + TILEB + rowOff + kOff + aLaneOff);
            }
#pragma unroll
            for (int nj = 0; nj < 2; nj++) {
                uint32_t rowOff = (uint32_t)((wn * 32 + nj * 16) * (STRH * 2));
                ldsm_x4(bH[nj], bp + 2 * TILEB + rowOff + kOff + bLaneOff);
                ldsm_x4(bL[nj], bp + 3 * TILEB + rowOff + kOff + bLaneOff);
            }
#pragma unroll
            for (int mi = 0; mi < 4; mi++)
#pragma unroll
                for (int ni = 0; ni < 4; ni++) {
                    uint32_t h0 = bH[ni >> 1][(ni & 1) * 2];
                    uint32_t h1 = bH[ni >> 1][(ni & 1) * 2 + 1];
                    uint32_t l0 = bL[ni >> 1][(ni & 1) * 2];
                    uint32_t l1 = bL[ni >> 1][(ni & 1) * 2 + 1];
                    mma16816(acc[mi][ni], aH[mi], h0, h1);   // hi*hi
                    mma16816(acc[mi][ni], aH[mi], l0, l1);   // hi*lo
                    mma16816(acc[mi][ni], aL[mi], h0, h1);   // lo*hi
                }
        }
        __syncthreads();   // before next iteration overwrites buf^1
    }

    // epilogue: bias add (fp32), split-store to hi/lo bf16 outputs
    const int qg = lid >> 2;
    const int qi = lid & 3;
#pragma unroll
    for (int ni = 0; ni < 4; ni++) {
        int col = n0 + wn * 32 + ni * 8 + qi * 2;
        float2 bb = *(const float2*)&bias[col];
#pragma unroll
        for (int mi = 0; mi < 4; mi++) {
            int row = m0 + wm * 64 + mi * 16 + qg;
            split2_store(Chi, Clo, (size_t)row * E_ + col,
                         acc[mi][ni][0] + bb.x, acc[mi][ni][1] + bb.y);
            split2_store(Chi, Clo, (size_t)(row + 8) * E_ + col,
                         acc[mi][ni][2] + bb.x, acc[mi][ni][3] + bb.y);
        }
    }
}

// ============================================================================
// Banded local attention, tensor cores + cp.async pipeline.
// Block = 32 queries. Key rows [q0-64, q0+95] -> 160, padded to 192.
// ============================================================================
#define TQ   32
#define NR   160
#define NRP  192
#define ACH  64
#define PSTR 200          // P smem stride (bf16)
#define SSTA 161          // scores fp32 stride

// per-stage layout (bytes)
#define SO_QHI 0
#define SO_QLO (SO_QHI + TQ * STRH * 2)        // 4608
#define SO_KHI (SO_QLO + TQ * STRH * 2)        // 9216
#define SO_KLO (SO_KHI + NRP * STRH * 2)       // 36864
#define ASTG   (SO_KLO + NRP * STRH * 2)       // 64512 per stage
#define O_SC   (2 * ASTG)                      // 129024
#define O_PHI  (O_SC + TQ * SSTA * 4)          // 149632
#define O_PLO  (O_PHI + TQ * PSTR * 2)         // 162432
#define A_SMEM (O_PLO + TQ * PSTR * 2)         // 175232 bytes

__global__ __launch_bounds__(256) void attn_tc(float* __restrict__ out)
{
    extern __shared__ __align__(16) char smem[];
    const uint32_t sb = smem_u32(smem);
    float* scS = (float*)(smem + O_SC);

    const int q0  = blockIdx.x * TQ;
    const int b   = blockIdx.y;
    const int t   = threadIdx.x;
    const int wid = t >> 5;
    const int lid = t & 31;
    const int g   = lid >> 3, r8 = lid & 7;
    const size_t base = (size_t)b * (L_ * E_);

    const uint32_t aOff  = (uint32_t)((((g & 1) * 8 + r8) * STRH + (g >> 1) * 8) * 2);
    const uint32_t bOff  = (uint32_t)((((g >> 1) * 8 + r8) * STRH + (g & 1) * 8) * 2);
    const uint32_t aPOff = (uint32_t)((((g & 1) * 8 + r8) * PSTR + (g >> 1) * 8) * 2);

    // ---- async chunk loaders ------------------------------------------------
    auto load_qk = [&](int ec, int stg) {
        const uint32_t sa = sb + (uint32_t)stg * ASTG;
        {   // Q tile 32x64
            int row = t >> 3, c8 = t & 7;
            uint32_t off = (uint32_t)(row * (STRH * 2) + c8 * 16);
            size_t gi = base + (size_t)(q0 + row) * E_ + ec + c8 * 8;
            cp16(sa + SO_QHI + off, g_qhi + gi);
            cp16(sa + SO_QLO + off, g_qlo + gi);
        }
#pragma unroll
        for (int it = 0; it < 5; it++) {    // K rows 0..159
            int idx = t + it * 256;
            int row = idx >> 3, c8 = idx & 7;
            int kg  = q0 - WIN + row;
            bool ok = (kg >= 0) && (kg < L_);
            size_t gi = base + (size_t)(ok ? kg : 0) * E_ + ec + c8 * 8;
            uint32_t off = (uint32_t)(row * (STRH * 2) + c8 * 16);
            cp16z(sa + SO_KHI + off, g_khi + gi, ok);
            cp16z(sa + SO_KLO + off, g_klo + gi, ok);
        }
    };
    auto load_v = [&](int ec, int stg) {
        const uint32_t sa = sb + (uint32_t)stg * ASTG;
#pragma unroll
        for (int it = 0; it < 5; it++) {    // V rows 0..159 (pad zeroed once)
            int idx = t + it * 256;
            int row = idx >> 3, c8 = idx & 7;
            int kg  = q0 - WIN + row;
            bool ok = (kg >= 0) && (kg < L_);
            size_t gi = base + (size_t)(ok ? kg : 0) * E_ + ec + c8 * 8;
            uint32_t off = (uint32_t)(row * (STRH * 2) + c8 * 16);
            cp16z(sa + SO_KHI + off, g_vhi + gi, ok);
            cp16z(sa + SO_KLO + off, g_vlo + gi, ok);
        }
    };

    // ---------------- Phase 1: S = Q K^T (pipelined over 8 e-chunks) -------
    float acc[2][3][4];
#pragma unroll
    for (int mi = 0; mi < 2; mi++)
#pragma unroll
        for (int nj = 0; nj < 3; nj++)
#pragma unroll
            for (int r = 0; r < 4; r++) acc[mi][nj][r] = 0.f;

    load_qk(0, 0);
    CP_COMMIT();

    for (int ci = 0; ci < 8; ci++) {
        const int stg = ci & 1;
        if (ci < 7) {
            load_qk((ci + 1) * ACH, stg ^ 1);
            CP_COMMIT();
            CP_WAIT(1);
        } else {
            CP_WAIT(0);
        }
        __syncthreads();

        const uint32_t sa = sb + (uint32_t)stg * ASTG;
#pragma unroll
        for (int kk = 0; kk < 4; kk++) {
            const uint32_t kOff = (uint32_t)(kk * 32);
            uint32_t aH[2][4], aL[2][4];
#pragma unroll
            for (int mi = 0; mi < 2; mi++) {
                uint32_t rowOff = (uint32_t)(mi * 16 * (STRH * 2));
                ldsm_x4(aH[mi], sa + SO_QHI + rowOff + kOff + aOff);
                ldsm_x4(aL[mi], sa + SO_QLO + rowOff + kOff + aOff);
            }
            const uint32_t nb0 = (uint32_t)(wid * 24 * (STRH * 2));
            const uint32_t nb1 = (uint32_t)((wid * 24 + 16) * (STRH * 2));
            uint32_t bH0[4], bH1[4], bL0[4], bL1[4];
            ldsm_x4(bH0, sa + SO_KHI + nb0 + kOff + bOff);
            ldsm_x4(bH1, sa + SO_KHI + nb1 + kOff + bOff);
            ldsm_x4(bL0, sa + SO_KLO + nb0 + kOff + bOff);
            ldsm_x4(bL1, sa + SO_KLO + nb1 + kOff + bOff);
#pragma unroll
            for (int mi = 0; mi < 2; mi++)
#pragma unroll
                for (int nj = 0; nj < 3; nj++) {
                    uint32_t h0 = (nj < 2) ? bH0[nj * 2]     : bH1[0];
                    uint32_t h1 = (nj < 2) ? bH0[nj * 2 + 1] : bH1[1];
                    uint32_t l0 = (nj < 2) ? bL0[nj * 2]     : bL1[0];
                    uint32_t l1 = (nj < 2) ? bL0[nj * 2 + 1] : bL1[1];
                    mma16816(acc[mi][nj], aH[mi], h0, h1);
                    mma16816(acc[mi][nj], aH[mi], l0, l1);
                    mma16816(acc[mi][nj], aL[mi], h0, h1);
                }
        }
        __syncthreads();
    }

    // write scores (n < 160 only) to fp32 smem
    {
        const int rA = lid >> 2, cA = (lid & 3) * 2;
#pragma unroll
        for (int mi = 0; mi < 2; mi++)
#pragma unroll
            for (int nj = 0; nj < 3; nj++) {
                int n = wid * 24 + nj * 8 + cA;
                if (n < NR) {
                    int r0 = mi * 16 + rA;
                    scS[r0 * SSTA + n]           = acc[mi][nj][0];
                    scS[r0 * SSTA + n + 1]       = acc[mi][nj][1];
                    scS[(r0 + 8) * SSTA + n]     = acc[mi][nj][2];
                    scS[(r0 + 8) * SSTA + n + 1] = acc[mi][nj][3];
                }
            }
    }

    // prefetch V chunk 0 into stage 0 while softmax runs
    load_v(0, 0);
    CP_COMMIT();

    // zero the pad rows (160..191) of BOTH stages once: 4 uint4 per thread
    {
        uint4 zz = make_uint4(0, 0, 0, 0);
#pragma unroll
        for (int s = 0; s < 2; s++) {
            int idx = t;                    // 256 threads cover 32 rows x 8 c8
            int row = NR + (idx >> 3), c8 = idx & 7;
            uint32_t off = (uint32_t)(row * (STRH * 2) + c8 * 16);
            char* sa = smem + s * ASTG;
            *(uint4*)(sa + SO_KHI + off) = zz;
            *(uint4*)(sa + SO_KLO + off) = zz;
        }
    }
    __syncthreads();

    // ---------------- Softmax (fp32), emit P as split bf16 ------------------
    {
        const float inv_sqrt_e = 0.04419417382415922f;  // 1/sqrt(512)
        const int qi  = t >> 3;
        const int sub = t & 7;
        float vals[20];
        float m = -INFINITY;
#pragma unroll
        for (int u = 0; u < 20; u++) {
            int r  = sub * 20 + u;
            int wj = r - qi;
            int kg = q0 + r - WIN;
            bool valid = (wj >= 0) && (wj <= 2 * WIN) && (kg >= 0) && (kg < L_);
            float s = valid ? scS[qi * SSTA + r] * inv_sqrt_e : -INFINITY;
            vals[u] = s;
            m = fmaxf(m, s);
        }
#pragma unroll
        for (int o = 1; o < 8; o <<= 1)
            m = fmaxf(m, __shfl_xor_sync(0xffffffffu, m, o, 8));
        float ssum = 0.f;
#pragma unroll
        for (int u = 0; u < 20; u++) {
            float e = (vals[u] == -INFINITY) ? 0.f : __expf(vals[u] - m);
            vals[u] = e;
            ssum += e;
        }
#pragma unroll
        for (int o = 1; o < 8; o <<= 1)
            ssum += __shfl_xor_sync(0xffffffffu, ssum, o, 8);
        float inv = 1.f / ssum;

        __nv_bfloat16* phi = (__nv_bfloat16*)(smem + O_PHI);
        __nv_bfloat16* plo = (__nv_bfloat16*)(smem + O_PLO);
#pragma unroll
        for (int u = 0; u < 20; u++) {
            float p = vals[u] * inv;
            __nv_bfloat16 h = __float2bfloat16(p);
            __nv_bfloat16 l = __float2bfloat16(p - __bfloat162float(h));
            phi[qi * PSTR + sub * 20 + u] = h;
            plo[qi * PSTR + sub * 20 + u] = l;
        }
        // zero pad columns 160..191 (k-dim padding for phase 2)
        __nv_bfloat16 z = __float2bfloat16(0.0f);
#pragma unroll
        for (int u = 0; u < 4; u++) {
            int r = NR + sub * 4 + u;
            phi[qi * PSTR + r] = z;
            plo[qi * PSTR + r] = z;
        }
    }
    __syncthreads();

    // ---------------- Phase 2: out = P @ V (pipelined over 8 e-chunks) -----
    float* gout = out + base;
    for (int ci = 0; ci < 8; ci++) {
        const int stg = ci & 1;
        if (ci < 7) {
            load_v((ci + 1) * ACH, stg ^ 1);
            CP_COMMIT();
            CP_WAIT(1);
        } else {
            CP_WAIT(0);
        }
        __syncthreads();

        const uint32_t sa = sb + (uint32_t)stg * ASTG;
        float o[2][4];
#pragma unroll
        for (int mi = 0; mi < 2; mi++)
#pragma unroll
            for (int r = 0; r < 4; r++) o[mi][r] = 0.f;

#pragma unroll
        for (int ks = 0; ks < 6; ks++) {   // k32 per iteration (192 total)
            uint32_t vrow = (uint32_t)((ks * 32 + lid) * (STRH * 2) + wid * 16);
            uint32_t vH[4], vL[4];
            ldsm_x4_t(vH, sa + SO_KHI + vrow);
            ldsm_x4_t(vL, sa + SO_KLO + vrow);
#pragma unroll
            for (int half = 0; half < 2; half++) {
                uint32_t kOff = (uint32_t)((ks * 32 + half * 16) * 2);
                uint32_t aH[2][4], aL[2][4];
#pragma unroll
                for (int mi = 0; mi < 2; mi++) {
                    uint32_t rowOff = (uint32_t)(mi * 16 * (PSTR * 2));
                    ldsm_x4(aH[mi], sb + O_PHI + rowOff + kOff + aPOff);
                    ldsm_x4(aL[mi], sb + O_PLO + rowOff + kOff + aPOff);
                }
                uint32_t h0 = vH[half * 2], h1 = vH[half * 2 + 1];
                uint32_t l0 = vL[half * 2], l1 = vL[half * 2 + 1];
#pragma unroll
                for (int mi = 0; mi < 2; mi++) {
                    mma16816(o[mi], aH[mi], h0, h1);   // Phi*Vhi
                    mma16816(o[mi], aH[mi], l0, l1);   // Phi*Vlo
                    mma16816(o[mi], aL[mi], h0, h1);   // Plo*Vhi
                }
            }
        }

        {   // store fp32 output
            int col = ci * ACH + wid * 8 + (lid & 3) * 2;
#pragma unroll
            for (int mi = 0; mi < 2; mi++) {
                int r = q0 + mi * 16 + (lid >> 2);
                *(float2*)&gout[(size_t)r * E_ + col] =
                    make_float2(o[mi][0], o[mi][1]);
                *(float2*)&gout[(size_t)(r + 8) * E_ + col] =
                    make_float2(o[mi][2], o[mi][3]);
            }
        }
        __syncthreads();
    }
}

// ============================================================================
extern "C" void kernel_launch(void* const* d_in, const int* in_sizes, int n_in,
                              void* d_out, int out_size)
{
    const float* x  = (const float*)d_in[0];
    const float* Wq = (const float*)d_in[1];
    const float* bq = (const float*)d_in[2];
    const float* Wk = (const float*)d_in[3];
    const float* bk = (const float*)d_in[4];
    const float* Wv = (const float*)d_in[5];
    const float* bv = (const float*)d_in[6];
    float* out = (float*)d_out;

    // 1) split X / W into bf16 hi/lo
    split_all<<<dim3(512, 4), 256>>>(x, Wq, Wk, Wv);

    // 2) QKV projections on tensor cores -> split bf16 q/k/v
    cudaFuncSetAttribute(qkv_tc, cudaFuncAttributeMaxDynamicSharedMemorySize,
                         QT_SMEM);
    dim3 ggrid((B_ * L_) / 128, E_ / 128, 3);
    qkv_tc<<<ggrid, 256, QT_SMEM>>>(bq, bk, bv);

    // 3) banded attention on tensor cores
    cudaFuncSetAttribute(attn_tc, cudaFuncAttributeMaxDynamicSharedMemorySize,
                         A_SMEM);
    dim3 agrid(L_ / TQ, B_);
    attn_tc<<<agrid, 256, A_SMEM>>>(out);
}